// round 10
// baseline (speedup 1.0000x reference)
#include <cuda_runtime.h>
#include <cuda_fp16.h>
#include <math.h>

#define NNODE 50000
#define EMB 35
#define DEG 32
#define NBH 40     // halves per feature row: 35 ch + s_b_even + s_b_odd + 3 pad = 80B (3 sectors)
#define MSTR 36    // g_m row stride (floats)

typedef unsigned long long ull;

// ---------------- scratch (device globals; no runtime allocation) ----------------
__device__ __half g_f16[2][NNODE * NBH];   // fp16 feature rows; side 0 = fa, 1 = fb
__device__ float  g_sa[4][NNODE];          // src-side attention score
__device__ float  g_m [4][NNODE * MSTR];   // aggregation results (raw-feature space)
__device__ float  g_W1f[2][105 * 72];      // per-side fused W1 (padded cols)
__device__ float  g_b1f[2][72];            // per-side fused bias
__device__ float  g_v[4][36];              // v_j = W_j @ att_hi (padded)
__device__ float  g_c[4];                  // c_j = b_j . att_hi

// ---------------- packed f32x2 helpers ----------------
static __device__ __forceinline__ ull pack2(float a, float b) {
    ull r;
    unsigned int lo = __float_as_uint(a), hi = __float_as_uint(b);
    asm("mov.b64 %0, {%1, %2};" : "=l"(r) : "r"(lo), "r"(hi));
    return r;
}
static __device__ __forceinline__ void unpack2(ull v, float &a, float &b) {
    unsigned int lo, hi;
    asm("mov.b64 {%0, %1}, %2;" : "=r"(lo), "=r"(hi) : "l"(v));
    a = __uint_as_float(lo);
    b = __uint_as_float(hi);
}
#define FMA2(d, a, b, c) \
    asm("fma.rn.f32x2 %0, %1, %2, %3;" : "=l"(d) : "l"(a), "l"(b), "l"(c))

// ---------------- kernel args ----------------
struct FArgs {
    const float* W[4];
    const float* b[4];
    const float* att[4];
    const float* W1;
    const float* b1;
};
struct CArgs {
    const float* fa;
    const float* fb;
    const float* att[4];
};
struct AArgs {
    const int* dst[4];
};

// =====================================================================
// Kernel 0: fuse. Per side s (block): jobs j0=2s, j0+1.
//   g_W1f[s] rows 0-34 = W1[0:35]; rows 35+r = W_j @ W1-block (fused)
//   g_b1f[s] = b1 + b_j0@W1[35:70] + b_j1@W1[70:105]
//   g_v[j] = W_j @ att_j_hi ; g_c[j] = b_j . att_j_hi
// =====================================================================
__global__ __launch_bounds__(256) void fuse_kernel(FArgs f) {
    const int s  = blockIdx.x;
    const int j0 = 2 * s;

    __shared__ float Wj[2][35 * 36];   // 10080B
    __shared__ float W1b[70 * 72];     // 20160B (W1 rows 35..104, padded)

    const int tid = threadIdx.x;
    for (int i = tid; i < 2 * 35 * 36; i += 256) {
        int p = i / (35 * 36), r = i % (35 * 36);
        int k = r / 36, c = r % 36;
        Wj[p][r] = (c < EMB) ? f.W[j0 + p][k * EMB + c] : 0.0f;
    }
    for (int i = tid; i < 70 * 72; i += 256) {
        int r = i / 72, c = i % 72;
        W1b[i] = (c < 70) ? f.W1[(35 + r) * 70 + c] : 0.0f;
    }
    __syncthreads();

    // rows 0-34: copy W1 with padding
    for (int i = tid; i < 35 * 72; i += 256) {
        int g = i / 72, c = i % 72;
        g_W1f[s][i] = (c < 70) ? f.W1[g * 70 + c] : 0.0f;
    }
    // fused rows 35..104
    for (int i = tid; i < 70 * 70; i += 256) {
        int r = i / 70, c = i % 70;
        int p = r / 35, k = r % 35;
        float acc = 0.0f;
        const float* wrow = &Wj[p][k * 36];
        const float* w1c  = &W1b[(35 * p) * 72 + c];
#pragma unroll 7
        for (int j = 0; j < 35; j++) acc = fmaf(wrow[j], w1c[j * 72], acc);
        g_W1f[s][(35 + r) * 72 + c] = acc;
    }
    // pad cols for fused rows
    for (int i = tid; i < 70 * 2; i += 256)
        g_W1f[s][(35 + i / 2) * 72 + 70 + (i & 1)] = 0.0f;

    // fused bias
    for (int c = tid; c < 72; c += 256) {
        if (c < 70) {
            float a = f.b1[c];
            for (int j = 0; j < EMB; j++) a = fmaf(f.b[j0][j],     W1b[j * 72 + c],        a);
            for (int j = 0; j < EMB; j++) a = fmaf(f.b[j0 + 1][j], W1b[(35 + j) * 72 + c], a);
            g_b1f[s][c] = a;
        } else {
            g_b1f[s][c] = 0.0f;
        }
    }

    // v_j and c_j for jobs j0, j0+1
    if (tid < 72) {
        int p = tid / 36, k = tid % 36;
        int j = j0 + p;
        float a = 0.0f;
        if (k < EMB) {
            const float* ah = f.att[j] + EMB;
#pragma unroll 7
            for (int c = 0; c < EMB; c++) a = fmaf(Wj[p][k * 36 + c], ah[c], a);
        }
        g_v[j][k] = a;
    }
    if (tid >= 72 && tid < 74) {
        int j = j0 + (tid - 72);
        float a = 0.0f;
        for (int c = 0; c < EMB; c++) a = fmaf(f.b[j][c], f.att[j][EMB + c], a);
        g_c[j] = a;
    }
}

// =====================================================================
// Kernel 1: cast + scores. Side s (gridDim.y): farr = (s ? fb : fa).
//   table g_f16[s]: 35 fp16 channels + slots 35/36 = s_b of the two jobs
//   whose fsrc == farr (jobs 2,3 for fa; 0,1 for fb).
//   g_sa for the two jobs whose fdst == farr (jobs 0,1 for fa; 2,3 for fb).
// 2 threads per row; features staged coalesced through smem.
// =====================================================================
__global__ __launch_bounds__(256) void cast_kernel(CArgs a) {
    const int s   = blockIdx.y;
    const int jb0 = s ? 0 : 2;    // s_b jobs (fsrc == farr)
    const int ja0 = s ? 2 : 0;    // s_a jobs (fdst == farr)
    const float* __restrict__ farr = s ? a.fb : a.fa;

    __shared__ __align__(16) float Xs[128 * 37];   // 18944B
    __shared__ float vsh[2][36];
    __shared__ float ash[2][36];
    __shared__ float csh[2];

    const int tid = threadIdx.x;
    if (tid < 72) {
        int p = tid / 36, k = tid % 36;
        vsh[p][k] = g_v[jb0 + p][k];
        ash[p][k] = (k < EMB) ? a.att[ja0 + p][k] : 0.0f;
    }
    if (tid < 2) csh[tid] = g_c[jb0 + tid];

    const int base  = blockIdx.x * 128;
    const int nrows = min(128, NNODE - base);
    const int total = nrows * EMB;
    {
        const float* __restrict__ src = farr + base * EMB;
        for (int g = tid; g < total; g += 256)
            Xs[(g / EMB) * 37 + (g % EMB)] = src[g];
    }
    __syncthreads();

    const int row_l = tid >> 1;
    const int half  = tid & 1;
    const bool valid = (row_l < nrows);
    const int rl = valid ? row_l : 0;
    const int row = base + rl;
    const float* xrs = Xs + rl * 37;

    float sbe = 0.0f, sbo = 0.0f;
    if (half == 0) {
        // s_a for both fdst jobs
        float s0 = 0.0f, s1 = 0.0f;
#pragma unroll 7
        for (int k = 0; k < EMB; k++) {
            float xv = xrs[k];
            s0 = fmaf(xv, ash[0][k], s0);
            s1 = fmaf(xv, ash[1][k], s1);
        }
        if (valid) {
            g_sa[ja0][row]     = s0;
            g_sa[ja0 + 1][row] = s1;
        }
    } else {
        // s_b for both fsrc jobs
        sbe = csh[0];
        sbo = csh[1];
#pragma unroll 7
        for (int k = 0; k < EMB; k++) {
            float xv = xrs[k];
            sbe = fmaf(xv, vsh[0][k], sbe);
            sbo = fmaf(xv, vsh[1][k], sbo);
        }
    }

    // fp16 cast: half h writes half-indices [20h, 20h+20) = 10 uints
    if (valid) {
        unsigned int* r =
            reinterpret_cast<unsigned int*>(&g_f16[s][row * NBH]) + 10 * half;
#pragma unroll
        for (int i = 0; i < 10; i++) {
            int i0 = 20 * half + 2 * i;
            float f0, f1;
            f0 = (i0 < EMB) ? xrs[i0] : ((i0 == 35) ? sbe : ((i0 == 36) ? sbo : 0.0f));
            int i1 = i0 + 1;
            f1 = (i1 < EMB) ? xrs[i1] : ((i1 == 35) ? sbe : ((i1 == 36) ? sbo : 0.0f));
            __half2 h = __floats2half2_rn(f0, f1);
            r[i] = *reinterpret_cast<unsigned int*>(&h);
        }
    }
}

// =====================================================================
// Kernel 2: attention aggregation over RAW fp16 features. One warp/node.
// Row = 10 ull (80B, always 3 sectors). s_b at slot 35 + (jid&1).
// Phase 2: lane = sub*9 + piece (pieces 0..8), 3 rows per warp LDG.64.
// Writes r = agg_raw/den to g_m (slot 35 garbage, never read).
// =====================================================================
__global__ __launch_bounds__(256) void agg_kernel(AArgs args) {
    const int jid = blockIdx.y;
    const __half* __restrict__ nbh16 = g_f16[(jid < 2) ? 1 : 0];
    const ull* __restrict__ nb = reinterpret_cast<const ull*>(nbh16);
    const float* __restrict__ sav = g_sa[jid];
    const int*   __restrict__ dst = args.dst[jid];
    float* __restrict__ m = g_m[jid];
    const int parity = jid & 1;

    __shared__ float sw[8][36];
    __shared__ int   soff[8][36];

    const int wid  = threadIdx.x >> 5;
    const int lane = threadIdx.x & 31;
    const int node = blockIdx.x * 8 + wid;
    if (node >= NNODE) return;

    const int d = dst[node * DEG + lane];
    float sb = __half2float(nbh16[d * NBH + 35 + parity]);
    float x = sav[node] + sb;
    float e = (x > 0.0f) ? x : 0.1f * expm1f(x);   // elu(alpha=0.1)
    float w = expf(e);

    float wsum = w;
#pragma unroll
    for (int o = 16; o; o >>= 1) wsum += __shfl_xor_sync(0xffffffffu, wsum, o);

    sw[wid][lane]   = w;
    soff[wid][lane] = d * 10;               // ull index of row start
    if (lane == 0) { sw[wid][32] = 0.0f; soff[wid][32] = 0; }
    __syncwarp();

    const int sub   = (lane < 27) ? (lane / 9) : 2;
    const int piece = (lane < 27) ? (lane % 9) : (lane - 27);

    float a0 = 0.0f, a1 = 0.0f, a2 = 0.0f, a3 = 0.0f;
#pragma unroll
    for (int it = 0; it < 11; it++) {
        int j = it * 3 + sub;
        float wj = sw[wid][j];
        ull v = nb[soff[wid][j] + piece];
        unsigned int lo, hi;
        asm("mov.b64 {%0, %1}, %2;" : "=r"(lo), "=r"(hi) : "l"(v));
        float2 f0 = __half22float2(*reinterpret_cast<__half2*>(&lo));
        float2 f1 = __half22float2(*reinterpret_cast<__half2*>(&hi));
        a0 = fmaf(wj, f0.x, a0);
        a1 = fmaf(wj, f0.y, a1);
        a2 = fmaf(wj, f1.x, a2);
        a3 = fmaf(wj, f1.y, a3);
    }

    {
        float t, u;
        t = __shfl_down_sync(0xffffffffu, a0, 9);
        u = __shfl_down_sync(0xffffffffu, a0, 18);
        a0 += t + u;
        t = __shfl_down_sync(0xffffffffu, a1, 9);
        u = __shfl_down_sync(0xffffffffu, a1, 18);
        a1 += t + u;
        t = __shfl_down_sync(0xffffffffu, a2, 9);
        u = __shfl_down_sync(0xffffffffu, a2, 18);
        a2 += t + u;
        t = __shfl_down_sync(0xffffffffu, a3, 9);
        u = __shfl_down_sync(0xffffffffu, a3, 18);
        a3 += t + u;
    }

    if (lane < 9) {
        float inv = 1.0f / wsum;
        float4 o = make_float4(a0 * inv, a1 * inv, a2 * inv, a3 * inv);
        *reinterpret_cast<float4*>(m + node * MSTR + 4 * lane) = o;
    }
}

// =====================================================================
// Kernel 3: out = prelu([feat, r0, r1] @ W1f + b1f) @ W2 + b2
// (W1f/b1f fused per side so r = raw-space aggregation is exact.)
// 4 threads per node; quad-cooperative x loads + width-4 shuffles.
// gridDim.y = side.
// =====================================================================
__global__ __launch_bounds__(256, 3) void update_kernel(
    const float* __restrict__ fa, const float* __restrict__ fb,
    const float* __restrict__ alpha_p,
    const float* __restrict__ W2, const float* __restrict__ b2,
    float* __restrict__ out)
{
    const int side = blockIdx.y;

    __shared__ __align__(16) float W1sh[105 * 72];   // 30240B
    __shared__ __align__(16) ull   w2p[70 * 18];     // 10080B
    __shared__ __align__(16) float hs[64 * 73];      // 18688B
    __shared__ __align__(16) ull b1p[36];
    __shared__ __align__(16) ull b2p[18];

    const int tid = threadIdx.x;
    {
        const float* __restrict__ src = g_W1f[side];
        for (int i = tid; i < 105 * 72; i += 256) W1sh[i] = src[i];
    }
    for (int i = tid; i < 70 * 18; i += 256) {
        int k = i / 18, j = i % 18;
        int c = 2 * j;
        w2p[i] = pack2(W2[k * EMB + c], (c + 1 < EMB) ? W2[k * EMB + c + 1] : 0.0f);
    }
    if (tid < 36) b1p[tid] = pack2(g_b1f[side][2 * tid], g_b1f[side][2 * tid + 1]);
    if (tid < 18) {
        int c = 2 * tid;
        b2p[tid] = pack2(b2[c], (c + 1 < EMB) ? b2[c + 1] : 0.0f);
    }
    __syncthreads();

    const int node_l = tid >> 2;
    const int role   = tid & 3;
    const int n      = blockIdx.x * 64 + node_l;      // node within side
    const bool valid = (n < NNODE);
    const int  nc    = valid ? n : (NNODE - 1);

    const float* xr = (side ? fb : fa) + nc * EMB;
    const float* m0 = g_m[2 * side]     + nc * MSTR;
    const float* m1 = g_m[2 * side + 1] + nc * MSTR;
    const float alpha = __ldg(alpha_p);

    // ---- quad-cooperative x load: this role owns x[g], g = 4*i + role ----
    float xv_[27];
#pragma unroll
    for (int i = 0; i < 27; i++) {
        int g = 4 * i + role;
        float v;
        if (g < EMB)            v = xr[g];
        else if (g < 2 * EMB)   v = m0[g - EMB];
        else if (g < 3 * EMB)   v = m1[g - 2 * EMB];
        else                    v = 0.0f;
        xv_[i] = v;
    }

    // ---- GEMM1: this role computes h pairs [9*role, 9*role+9) ----
    ull acc[9];
#pragma unroll
    for (int i = 0; i < 9; i++) acc[i] = b1p[9 * role + i];

    const ull* w1base = reinterpret_cast<const ull*>(W1sh) + 9 * role;
#pragma unroll
    for (int k = 0; k < 105; k++) {
        float xv = __shfl_sync(0xffffffffu, xv_[k >> 2], k & 3, 4);
        ull xx = pack2(xv, xv);
        const ull* wr = w1base + k * 36;
#pragma unroll
        for (int i = 0; i < 9; i++) FMA2(acc[i], wr[i], xx, acc[i]);
    }

    // ---- PReLU, publish h to smem (quad lives in one warp) ----
    float* hrow = hs + node_l * 73;
#pragma unroll
    for (int i = 0; i < 9; i++) {
        float h0, h1;
        unpack2(acc[i], h0, h1);
        h0 = (h0 > 0.0f) ? h0 : alpha * h0;
        h1 = (h1 > 0.0f) ? h1 : alpha * h1;
        int c = 18 * role + 2 * i;
        hrow[c]     = h0;
        hrow[c + 1] = h1;
    }
    __syncwarp();

    // ---- GEMM2: role owns output pairs [p0, p0+np) ----
    const int p0 = (role < 2) ? role * 5 : 10 + (role - 2) * 4;
    const int np = (role < 2) ? 5 : 4;

    ull acc2[5];
#pragma unroll
    for (int q = 0; q < 5; q++) acc2[q] = (q < np) ? b2p[p0 + q] : 0ull;

#pragma unroll 2
    for (int k = 0; k < 70; k++) {
        float hv = hrow[k];
        ull xx = pack2(hv, hv);
        const ull* wr = w2p + k * 18 + p0;
#pragma unroll
        for (int q = 0; q < 5; q++)
            if (q < np) FMA2(acc2[q], wr[q], xx, acc2[q]);
    }

    if (valid) {
        float* orow = out + (side * NNODE + n) * EMB;
#pragma unroll
        for (int q = 0; q < 5; q++) {
            if (q < np) {
                float v0, v1;
                unpack2(acc2[q], v0, v1);
                int c = 2 * (p0 + q);
                orow[c] = v0;
                if (c + 1 < EMB) orow[c + 1] = v1;
            }
        }
    }
}

// =====================================================================
// launch
// =====================================================================
extern "C" void kernel_launch(void* const* d_in, const int* in_sizes, int n_in,
                              void* d_out, int out_size) {
    const float* fa = (const float*)d_in[0];
    const float* fb = (const float*)d_in[1];

    FArgs f;
    for (int j = 0; j < 4; j++) {
        f.W[j]   = (const float*)d_in[6 + 3 * j];
        f.b[j]   = (const float*)d_in[7 + 3 * j];
        f.att[j] = (const float*)d_in[8 + 3 * j];
    }
    f.W1 = (const float*)d_in[18];
    f.b1 = (const float*)d_in[19];

    CArgs c;
    c.fa = fa;
    c.fb = fb;
    for (int j = 0; j < 4; j++) c.att[j] = f.att[j];

    AArgs a;
    a.dst[0] = (const int*)d_in[2];
    a.dst[1] = (const int*)d_in[3];
    a.dst[2] = (const int*)d_in[4];
    a.dst[3] = (const int*)d_in[5];

    const float* al = (const float*)d_in[20];
    const float* W2 = (const float*)d_in[21];
    const float* b2 = (const float*)d_in[22];
    float* out = (float*)d_out;

    fuse_kernel<<<2, 256>>>(f);

    dim3 cg((NNODE + 127) / 128, 2);
    cast_kernel<<<cg, 256>>>(c);

    dim3 ag((NNODE + 7) / 8, 4);
    agg_kernel<<<ag, 256>>>(a);

    dim3 ug((NNODE + 63) / 64, 2);
    update_kernel<<<ug, 256>>>(fa, fb, al, W2, b2, out);
}

// round 11
// speedup vs baseline: 1.0636x; 1.0636x over previous
#include <cuda_runtime.h>
#include <cuda_fp16.h>
#include <math.h>

#define NNODE 50000
#define EMB 35
#define DEG 32
#define NBH 36     // halves per nb row: 35 ch + s_b(fp16) at slot 35 = 72B = 9 ull
#define MSTR 36    // g_m row stride (floats)

typedef unsigned long long ull;

// ---------------- scratch (device globals; no runtime allocation) ----------------
__device__ __half g_nbh[4][NNODE * NBH];   // fp16 transformed rows; slot 35 carries s_b
__device__ float  g_sa[4][NNODE];          // src-side attention score
__device__ float  g_m [4][NNODE * MSTR];   // aggregation results (padded rows)

// ---------------- packed f32x2 helpers ----------------
static __device__ __forceinline__ ull pack2(float a, float b) {
    ull r;
    unsigned int lo = __float_as_uint(a), hi = __float_as_uint(b);
    asm("mov.b64 %0, {%1, %2};" : "=l"(r) : "r"(lo), "r"(hi));
    return r;
}
static __device__ __forceinline__ void unpack2(ull v, float &a, float &b) {
    unsigned int lo, hi;
    asm("mov.b64 {%0, %1}, %2;" : "=r"(lo), "=r"(hi) : "l"(v));
    a = __uint_as_float(lo);
    b = __uint_as_float(hi);
}
#define FMA2(d, a, b, c) \
    asm("fma.rn.f32x2 %0, %1, %2, %3;" : "=l"(d) : "l"(a), "l"(b), "l"(c))

// ---------------- kernel args ----------------
struct TArgs {
    const float* fsrc[4];
    const float* fdst[4];
    const float* W[4];
    const float* b[4];
    const float* att[4];
};
struct AArgs {
    const int* dst[4];
};

// =====================================================================
// Kernel 1 (R9 form): nb = fsrc @ W + b (fp16, s_b folded into slot 35);
//           s_a = fdst . att_lo. Two-phase smem staging.
// 2 threads per row (half-channel split). jobs on gridDim.y.
// =====================================================================
__global__ __launch_bounds__(256) void transform_kernel(TArgs args) {
    const int jid = blockIdx.y;
    const float* __restrict__ bv  = args.b[jid];
    const float* __restrict__ att = args.att[jid];

    __shared__ __align__(16) float Xs[128 * 37];    // 18944B staged feature rows
    __shared__ __align__(16) ull wp[EMB * 18];      // 5040B packed W col-pairs
    __shared__ __align__(16) ull bp[18];
    __shared__ __align__(16) ull ahp[18];
    __shared__ __align__(16) float alo[36];

    const int tid = threadIdx.x;
    {
        const float* __restrict__ W = args.W[jid];
        for (int r = tid; r < EMB * 18; r += 256) {
            int k = r / 18, i = r % 18, c = 2 * i;
            wp[r] = pack2(W[k * EMB + c], (c + 1 < EMB) ? W[k * EMB + c + 1] : 0.0f);
        }
    }
    if (tid < 18) {
        int c = 2 * tid;
        bp[tid]  = pack2(bv[c],        (c + 1 < EMB) ? bv[c + 1]        : 0.0f);
        ahp[tid] = pack2(att[EMB + c], (c + 1 < EMB) ? att[EMB + c + 1] : 0.0f);
    }
    if (tid < 36) alo[tid] = (tid < EMB) ? att[tid] : 0.0f;

    const int base  = blockIdx.x * 128;
    const int nrows = min(128, NNODE - base);
    const int total = nrows * EMB;

    const int row_l = tid >> 1;
    const int half  = tid & 1;
    const bool valid = (row_l < nrows);
    const int rl = valid ? row_l : 0;
    const int row = base + rl;
    const float* xrs = Xs + rl * 37;

    // ---- phase A: stage fdst, compute s_a ----
    {
        const float* __restrict__ src = args.fdst[jid] + base * EMB;
        for (int g = tid; g < total; g += 256)
            Xs[(g / EMB) * 37 + (g % EMB)] = src[g];
    }
    __syncthreads();
    {
        float sa = 0.0f;
        const int k0 = half ? 18 : 0;
        const int k1 = half ? EMB : 18;
        for (int k = k0; k < k1; k++) sa = fmaf(xrs[k], alo[k], sa);
        sa += __shfl_xor_sync(0xffffffffu, sa, 1);
        if (valid && half == 0) g_sa[jid][row] = sa;
    }
    __syncthreads();

    // ---- phase B: stage fsrc, GEMM + s_b ----
    {
        const float* __restrict__ src = args.fsrc[jid] + base * EMB;
        for (int g = tid; g < total; g += 256)
            Xs[(g / EMB) * 37 + (g % EMB)] = src[g];
    }
    __syncthreads();

    ull acc[9];
#pragma unroll
    for (int i = 0; i < 9; i++) acc[i] = bp[9 * half + i];

#pragma unroll 5
    for (int k = 0; k < EMB; k++) {
        float xv = xrs[k];
        ull xx = pack2(xv, xv);
        const ull* wr = wp + k * 18 + 9 * half;
#pragma unroll
        for (int i = 0; i < 9; i++) FMA2(acc[i], wr[i], xx, acc[i]);
    }

    float ps;
    {
        ull sp = 0ull;
#pragma unroll
        for (int i = 0; i < 9; i++) FMA2(sp, acc[i], ahp[9 * half + i], sp);
        float x0, y0;
        unpack2(sp, x0, y0);
        ps = x0 + y0;
        ps += __shfl_xor_sync(0xffffffffu, ps, 1);
    }

    if (valid) {
        unsigned int* r =
            reinterpret_cast<unsigned int*>(&g_nbh[jid][row * NBH]) + 9 * half;
#pragma unroll
        for (int i = 0; i < 9; i++) {
            float f0, f1;
            unpack2(acc[i], f0, f1);
            if (half == 1 && i == 8) f1 = ps;    // slot 35 := s_b
            __half2 h = __floats2half2_rn(f0, f1);
            r[i] = *reinterpret_cast<unsigned int*>(&h);
        }
    }
}

// =====================================================================
// Kernel 2 (R9 form): attention aggregation. One warp per node.
// s_b read from row slot 35. Row = 9 x 8B; 3 edges per warp LDG.64 iter.
// =====================================================================
__global__ __launch_bounds__(256) void agg_kernel(AArgs args) {
    const int jid = blockIdx.y;
    const __half* __restrict__ nbh = g_nbh[jid];
    const ull* __restrict__ nb = reinterpret_cast<const ull*>(nbh);
    const float* __restrict__ sav = g_sa[jid];
    const int*   __restrict__ dst = args.dst[jid];
    float* __restrict__ m = g_m[jid];

    __shared__ float sw[8][36];
    __shared__ int   soff[8][36];

    const int wid  = threadIdx.x >> 5;
    const int lane = threadIdx.x & 31;
    const int node = blockIdx.x * 8 + wid;
    if (node >= NNODE) return;

    const int d = dst[node * DEG + lane];
    float sb = __half2float(nbh[d * NBH + 35]);
    float x = sav[node] + sb;
    float e = (x > 0.0f) ? x : 0.1f * expm1f(x);   // elu(alpha=0.1)
    float w = expf(e);

    float wsum = w;
#pragma unroll
    for (int o = 16; o; o >>= 1) wsum += __shfl_xor_sync(0xffffffffu, wsum, o);

    sw[wid][lane]   = w;
    soff[wid][lane] = d * 9;
    if (lane == 0) { sw[wid][32] = 0.0f; soff[wid][32] = 0; }
    __syncwarp();

    const int sub   = (lane < 27) ? (lane / 9) : 2;
    const int piece = (lane < 27) ? (lane % 9) : (lane - 27);

    float a0 = 0.0f, a1 = 0.0f, a2 = 0.0f, a3 = 0.0f;
#pragma unroll
    for (int it = 0; it < 11; it++) {
        int j = it * 3 + sub;
        float wj = sw[wid][j];
        ull v = nb[soff[wid][j] + piece];
        unsigned int lo, hi;
        asm("mov.b64 {%0, %1}, %2;" : "=r"(lo), "=r"(hi) : "l"(v));
        float2 f0 = __half22float2(*reinterpret_cast<__half2*>(&lo));
        float2 f1 = __half22float2(*reinterpret_cast<__half2*>(&hi));
        a0 = fmaf(wj, f0.x, a0);
        a1 = fmaf(wj, f0.y, a1);
        a2 = fmaf(wj, f1.x, a2);
        a3 = fmaf(wj, f1.y, a3);
    }

    {
        float t, u;
        t = __shfl_down_sync(0xffffffffu, a0, 9);
        u = __shfl_down_sync(0xffffffffu, a0, 18);
        a0 += t + u;
        t = __shfl_down_sync(0xffffffffu, a1, 9);
        u = __shfl_down_sync(0xffffffffu, a1, 18);
        a1 += t + u;
        t = __shfl_down_sync(0xffffffffu, a2, 9);
        u = __shfl_down_sync(0xffffffffu, a2, 18);
        a2 += t + u;
        t = __shfl_down_sync(0xffffffffu, a3, 9);
        u = __shfl_down_sync(0xffffffffu, a3, 18);
        a3 += t + u;
    }

    if (lane < 9) {
        float inv = 1.0f / wsum;
        float4 o = make_float4(a0 * inv, a1 * inv, a2 * inv, a3 * inv);
        *reinterpret_cast<float4*>(m + node * MSTR + 4 * lane) = o;
    }
}

// =====================================================================
// Kernel 3 (NEW): register-tiled update.
// Block = 128 nodes, 256 threads = 4 col-groups x 64 node-groups.
// Thread owns 2 nodes x 18 cols. X staged transposed+packed in smem
// (Xp[k][node], pad 130): per k, 9 broadcast W-LDS + 1 x-LDS feed 18 FMA2.
// GEMM2 reuses the Xp buffer as Hp[c][node] after a barrier.
// =====================================================================
__global__ __launch_bounds__(256, 2) void update_kernel(
    const float* __restrict__ fa, const float* __restrict__ fb,
    const float* __restrict__ W1, const float* __restrict__ b1,
    const float* __restrict__ alpha_p,
    const float* __restrict__ W2, const float* __restrict__ b2,
    float* __restrict__ out)
{
    __shared__ __align__(16) float Xs[105 * 130];   // 54600B: Xp, then Hp
    __shared__ __align__(16) ull   w1p[105 * 36];   // 30240B packed W1 col pairs
    __shared__ __align__(16) ull   w2p[70 * 18];    // 10080B packed W2 col pairs
    __shared__ __align__(16) ull   b1p[36];
    __shared__ __align__(16) ull   b2p[18];

    const int tid = threadIdx.x;
    for (int i = tid; i < 105 * 36; i += 256) {
        int k = i / 36, j = i % 36;
        int c = 2 * j;
        float v0 = (c < 70)     ? W1[k * 70 + c]     : 0.0f;
        float v1 = (c + 1 < 70) ? W1[k * 70 + c + 1] : 0.0f;
        w1p[i] = pack2(v0, v1);
    }
    for (int i = tid; i < 70 * 18; i += 256) {
        int k = i / 18, j = i % 18;
        int c = 2 * j;
        w2p[i] = pack2(W2[k * EMB + c], (c + 1 < EMB) ? W2[k * EMB + c + 1] : 0.0f);
    }
    if (tid < 36) {
        int c = 2 * tid;
        b1p[tid] = pack2((c < 70) ? b1[c] : 0.0f, (c + 1 < 70) ? b1[c + 1] : 0.0f);
    }
    if (tid < 18) {
        int c = 2 * tid;
        b2p[tid] = pack2(b2[c], (c + 1 < EMB) ? b2[c + 1] : 0.0f);
    }

    const int base = blockIdx.x * 128;

    // ---- stage X transposed: Xs[k*130 + node_l] = x[node][k] ----
    for (int g = tid; g < 128 * 105; g += 256) {
        int nl = g / 105;
        int k  = g - nl * 105;
        int n  = base + nl;
        float v = 0.0f;
        if (n < 2 * NNODE) {
            if (n < NNODE) {
                if (k < EMB)          v = fa[n * EMB + k];
                else if (k < 2 * EMB) v = g_m[0][n * MSTR + (k - EMB)];
                else                  v = g_m[1][n * MSTR + (k - 2 * EMB)];
            } else {
                int nn = n - NNODE;
                if (k < EMB)          v = fb[nn * EMB + k];
                else if (k < 2 * EMB) v = g_m[2][nn * MSTR + (k - EMB)];
                else                  v = g_m[3][nn * MSTR + (k - 2 * EMB)];
            }
        }
        Xs[k * 130 + nl] = v;
    }
    __syncthreads();

    const int cg = tid >> 6;          // 0..3: column group (18 cols = 9 pairs)
    const int ng = tid & 63;          // 0..63: node pair
    const int n0 = base + 2 * ng;
    const float alpha = __ldg(alpha_p);

    // ---- GEMM1: 2 nodes x 9 pairs ----
    ull acc0[9], acc1[9];
#pragma unroll
    for (int i = 0; i < 9; i++) { acc0[i] = b1p[9 * cg + i]; acc1[i] = acc0[i]; }

    const ull* wbase = w1p + 9 * cg;
    for (int k = 0; k < 105; k++) {
        float2 xv = *reinterpret_cast<const float2*>(&Xs[k * 130 + 2 * ng]);
        ull xx0 = pack2(xv.x, xv.x);
        ull xx1 = pack2(xv.y, xv.y);
        const ull* wr = wbase + k * 36;
#pragma unroll
        for (int i = 0; i < 9; i++) {
            ull w = wr[i];
            FMA2(acc0[i], w, xx0, acc0[i]);
            FMA2(acc1[i], w, xx1, acc1[i]);
        }
    }
    __syncthreads();   // all Xp reads complete; buffer becomes Hp

    // ---- PReLU, publish Hp[c][node_l] ----
#pragma unroll
    for (int i = 0; i < 9; i++) {
        int c = 18 * cg + 2 * i;
        float h0, h1;
        unpack2(acc0[i], h0, h1);
        h0 = (h0 > 0.0f) ? h0 : alpha * h0;
        h1 = (h1 > 0.0f) ? h1 : alpha * h1;
        Xs[c * 130 + 2 * ng]       = h0;
        Xs[(c + 1) * 130 + 2 * ng] = h1;
        unpack2(acc1[i], h0, h1);
        h0 = (h0 > 0.0f) ? h0 : alpha * h0;
        h1 = (h1 > 0.0f) ? h1 : alpha * h1;
        Xs[c * 130 + 2 * ng + 1]       = h0;
        Xs[(c + 1) * 130 + 2 * ng + 1] = h1;
    }
    __syncthreads();

    // ---- GEMM2: 2 nodes x np output pairs (bias owned fully) ----
    const int p0 = (cg < 2) ? cg * 5 : 10 + (cg - 2) * 4;
    const int np = (cg < 2) ? 5 : 4;

    ull a20[5], a21[5];
#pragma unroll
    for (int q = 0; q < 5; q++) {
        ull b = (q < np) ? b2p[p0 + q] : 0ull;
        a20[q] = b;
        a21[q] = b;
    }

    const ull* w2base = w2p + p0;
    for (int k = 0; k < 70; k++) {
        float2 hv = *reinterpret_cast<const float2*>(&Xs[k * 130 + 2 * ng]);
        ull xx0 = pack2(hv.x, hv.x);
        ull xx1 = pack2(hv.y, hv.y);
        const ull* wr = w2base + k * 18;
#pragma unroll
        for (int q = 0; q < 5; q++) {
            if (q < np) {
                ull w = wr[q];
                FMA2(a20[q], w, xx0, a20[q]);
                FMA2(a21[q], w, xx1, a21[q]);
            }
        }
    }

    // ---- write both nodes' output slices ----
#pragma unroll
    for (int p = 0; p < 2; p++) {
        int n = n0 + p;
        if (n < 2 * NNODE) {
            float* orow = out + n * EMB;
#pragma unroll
            for (int q = 0; q < 5; q++) {
                if (q < np) {
                    float v0, v1;
                    unpack2(p ? a21[q] : a20[q], v0, v1);
                    int c = 2 * (p0 + q);
                    orow[c] = v0;
                    if (c + 1 < EMB) orow[c + 1] = v1;
                }
            }
        }
    }
}

// =====================================================================
// launch
// =====================================================================
extern "C" void kernel_launch(void* const* d_in, const int* in_sizes, int n_in,
                              void* d_out, int out_size) {
    const float* fa = (const float*)d_in[0];
    const float* fb = (const float*)d_in[1];

    TArgs t;
    const float* fsrc[4] = { fb, fb, fa, fa };
    const float* fdst[4] = { fa, fa, fb, fb };
    for (int j = 0; j < 4; j++) {
        t.fsrc[j] = fsrc[j];
        t.fdst[j] = fdst[j];
        t.W[j]   = (const float*)d_in[6 + 3 * j];
        t.b[j]   = (const float*)d_in[7 + 3 * j];
        t.att[j] = (const float*)d_in[8 + 3 * j];
    }
    AArgs a;
    a.dst[0] = (const int*)d_in[2];
    a.dst[1] = (const int*)d_in[3];
    a.dst[2] = (const int*)d_in[4];
    a.dst[3] = (const int*)d_in[5];

    const float* W1 = (const float*)d_in[18];
    const float* b1 = (const float*)d_in[19];
    const float* al = (const float*)d_in[20];
    const float* W2 = (const float*)d_in[21];
    const float* b2 = (const float*)d_in[22];
    float* out = (float*)d_out;

    dim3 tg((NNODE + 127) / 128, 4);
    transform_kernel<<<tg, 256>>>(t);

    dim3 ag((NNODE + 7) / 8, 4);
    agg_kernel<<<ag, 256>>>(a);

    dim3 ug((2 * NNODE + 127) / 128);
    update_kernel<<<ug, 256>>>(fa, fb, W1, b1, al, W2, b2, out);
}

// round 12
// speedup vs baseline: 1.1335x; 1.0658x over previous
#include <cuda_runtime.h>
#include <cuda_fp16.h>
#include <math.h>

#define NNODE 50000
#define EMB 35
#define DEG 32
#define NBH 36     // halves per nb row: 35 ch + s_b(fp16) at slot 35 = 72B = 9 ull
#define MSTR 36    // g_m row stride (floats)

typedef unsigned long long ull;

// ---------------- scratch (device globals; no runtime allocation) ----------------
__device__ __half g_nbh[4][NNODE * NBH];   // fp16 transformed rows; slot 35 carries s_b
__device__ float  g_sa[4][NNODE];          // src-side attention score
__device__ float  g_m [4][NNODE * MSTR];   // aggregation results (padded rows)

// ---------------- packed f32x2 helpers ----------------
static __device__ __forceinline__ ull pack2(float a, float b) {
    ull r;
    unsigned int lo = __float_as_uint(a), hi = __float_as_uint(b);
    asm("mov.b64 %0, {%1, %2};" : "=l"(r) : "r"(lo), "r"(hi));
    return r;
}
static __device__ __forceinline__ void unpack2(ull v, float &a, float &b) {
    unsigned int lo, hi;
    asm("mov.b64 {%0, %1}, %2;" : "=r"(lo), "=r"(hi) : "l"(v));
    a = __uint_as_float(lo);
    b = __uint_as_float(hi);
}
#define FMA2(d, a, b, c) \
    asm("fma.rn.f32x2 %0, %1, %2, %3;" : "=l"(d) : "l"(a), "l"(b), "l"(c))

// ---------------- kernel args ----------------
struct TArgs {
    const float* fsrc[4];
    const float* fdst[4];
    const float* W[4];
    const float* b[4];
    const float* att[4];
};
struct AArgs {
    const int* dst[4];
};

// =====================================================================
// Kernel 1 (R9/R11 form): nb = fsrc @ W + b (fp16, s_b in slot 35);
//           s_a = fdst . att_lo. Two-phase smem staging.
// =====================================================================
__global__ __launch_bounds__(256) void transform_kernel(TArgs args) {
    const int jid = blockIdx.y;
    const float* __restrict__ bv  = args.b[jid];
    const float* __restrict__ att = args.att[jid];

    __shared__ __align__(16) float Xs[128 * 37];    // 18944B staged feature rows
    __shared__ __align__(16) ull wp[EMB * 18];      // 5040B packed W col-pairs
    __shared__ __align__(16) ull bp[18];
    __shared__ __align__(16) ull ahp[18];
    __shared__ __align__(16) float alo[36];

    const int tid = threadIdx.x;
    {
        const float* __restrict__ W = args.W[jid];
        for (int r = tid; r < EMB * 18; r += 256) {
            int k = r / 18, i = r % 18, c = 2 * i;
            wp[r] = pack2(W[k * EMB + c], (c + 1 < EMB) ? W[k * EMB + c + 1] : 0.0f);
        }
    }
    if (tid < 18) {
        int c = 2 * tid;
        bp[tid]  = pack2(bv[c],        (c + 1 < EMB) ? bv[c + 1]        : 0.0f);
        ahp[tid] = pack2(att[EMB + c], (c + 1 < EMB) ? att[EMB + c + 1] : 0.0f);
    }
    if (tid < 36) alo[tid] = (tid < EMB) ? att[tid] : 0.0f;

    const int base  = blockIdx.x * 128;
    const int nrows = min(128, NNODE - base);
    const int total = nrows * EMB;

    const int row_l = tid >> 1;
    const int half  = tid & 1;
    const bool valid = (row_l < nrows);
    const int rl = valid ? row_l : 0;
    const int row = base + rl;
    const float* xrs = Xs + rl * 37;

    // ---- phase A: stage fdst, compute s_a ----
    {
        const float* __restrict__ src = args.fdst[jid] + base * EMB;
        for (int g = tid; g < total; g += 256)
            Xs[(g / EMB) * 37 + (g % EMB)] = src[g];
    }
    __syncthreads();
    {
        float sa = 0.0f;
        const int k0 = half ? 18 : 0;
        const int k1 = half ? EMB : 18;
        for (int k = k0; k < k1; k++) sa = fmaf(xrs[k], alo[k], sa);
        sa += __shfl_xor_sync(0xffffffffu, sa, 1);
        if (valid && half == 0) g_sa[jid][row] = sa;
    }
    __syncthreads();

    // ---- phase B: stage fsrc, GEMM + s_b ----
    {
        const float* __restrict__ src = args.fsrc[jid] + base * EMB;
        for (int g = tid; g < total; g += 256)
            Xs[(g / EMB) * 37 + (g % EMB)] = src[g];
    }
    __syncthreads();

    ull acc[9];
#pragma unroll
    for (int i = 0; i < 9; i++) acc[i] = bp[9 * half + i];

#pragma unroll 5
    for (int k = 0; k < EMB; k++) {
        float xv = xrs[k];
        ull xx = pack2(xv, xv);
        const ull* wr = wp + k * 18 + 9 * half;
#pragma unroll
        for (int i = 0; i < 9; i++) FMA2(acc[i], wr[i], xx, acc[i]);
    }

    float ps;
    {
        ull sp = 0ull;
#pragma unroll
        for (int i = 0; i < 9; i++) FMA2(sp, acc[i], ahp[9 * half + i], sp);
        float x0, y0;
        unpack2(sp, x0, y0);
        ps = x0 + y0;
        ps += __shfl_xor_sync(0xffffffffu, ps, 1);
    }

    if (valid) {
        unsigned int* r =
            reinterpret_cast<unsigned int*>(&g_nbh[jid][row * NBH]) + 9 * half;
#pragma unroll
        for (int i = 0; i < 9; i++) {
            float f0, f1;
            unpack2(acc[i], f0, f1);
            if (half == 1 && i == 8) f1 = ps;    // slot 35 := s_b
            __half2 h = __floats2half2_rn(f0, f1);
            r[i] = *reinterpret_cast<unsigned int*>(&h);
        }
    }
}

// =====================================================================
// Kernel 2 (R11 form): attention aggregation. One warp per node.
// =====================================================================
__global__ __launch_bounds__(256) void agg_kernel(AArgs args) {
    const int jid = blockIdx.y;
    const __half* __restrict__ nbh = g_nbh[jid];
    const ull* __restrict__ nb = reinterpret_cast<const ull*>(nbh);
    const float* __restrict__ sav = g_sa[jid];
    const int*   __restrict__ dst = args.dst[jid];
    float* __restrict__ m = g_m[jid];

    __shared__ float sw[8][36];
    __shared__ int   soff[8][36];

    const int wid  = threadIdx.x >> 5;
    const int lane = threadIdx.x & 31;
    const int node = blockIdx.x * 8 + wid;
    if (node >= NNODE) return;

    const int d = dst[node * DEG + lane];
    float sb = __half2float(nbh[d * NBH + 35]);
    float x = sav[node] + sb;
    float e = (x > 0.0f) ? x : 0.1f * expm1f(x);   // elu(alpha=0.1)
    float w = expf(e);

    float wsum = w;
#pragma unroll
    for (int o = 16; o; o >>= 1) wsum += __shfl_xor_sync(0xffffffffu, wsum, o);

    sw[wid][lane]   = w;
    soff[wid][lane] = d * 9;
    if (lane == 0) { sw[wid][32] = 0.0f; soff[wid][32] = 0; }
    __syncwarp();

    const int sub   = (lane < 27) ? (lane / 9) : 2;
    const int piece = (lane < 27) ? (lane % 9) : (lane - 27);

    float a0 = 0.0f, a1 = 0.0f, a2 = 0.0f, a3 = 0.0f;
#pragma unroll
    for (int it = 0; it < 11; it++) {
        int j = it * 3 + sub;
        float wj = sw[wid][j];
        ull v = nb[soff[wid][j] + piece];
        unsigned int lo, hi;
        asm("mov.b64 {%0, %1}, %2;" : "=r"(lo), "=r"(hi) : "l"(v));
        float2 f0 = __half22float2(*reinterpret_cast<__half2*>(&lo));
        float2 f1 = __half22float2(*reinterpret_cast<__half2*>(&hi));
        a0 = fmaf(wj, f0.x, a0);
        a1 = fmaf(wj, f0.y, a1);
        a2 = fmaf(wj, f1.x, a2);
        a3 = fmaf(wj, f1.y, a3);
    }

    {
        float t, u;
        t = __shfl_down_sync(0xffffffffu, a0, 9);
        u = __shfl_down_sync(0xffffffffu, a0, 18);
        a0 += t + u;
        t = __shfl_down_sync(0xffffffffu, a1, 9);
        u = __shfl_down_sync(0xffffffffu, a1, 18);
        a1 += t + u;
        t = __shfl_down_sync(0xffffffffu, a2, 9);
        u = __shfl_down_sync(0xffffffffu, a2, 18);
        a2 += t + u;
        t = __shfl_down_sync(0xffffffffu, a3, 9);
        u = __shfl_down_sync(0xffffffffu, a3, 18);
        a3 += t + u;
    }

    if (lane < 9) {
        float inv = 1.0f / wsum;
        float4 o = make_float4(a0 * inv, a1 * inv, a2 * inv, a3 * inv);
        *reinterpret_cast<float4*>(m + node * MSTR + 4 * lane) = o;
    }
}

// =====================================================================
// Kernel 3: register-tiled update with fp16 X/H staging (3 blocks/SM).
// Block = 128 nodes, 256 threads = 4 col-groups x 64 node-pairs.
// Thread owns 2 nodes x 18 cols. Xh[k][node] half: one LDS.32 yields both
// nodes' x_k. Hh reuses the same buffer for GEMM2.
// =====================================================================
__global__ __launch_bounds__(256, 3) void update_kernel(
    const float* __restrict__ fa, const float* __restrict__ fb,
    const float* __restrict__ W1, const float* __restrict__ b1,
    const float* __restrict__ alpha_p,
    const float* __restrict__ W2, const float* __restrict__ b2,
    float* __restrict__ out)
{
    __shared__ __align__(16) __half Xh[105 * 132];  // 27720B: Xh, then Hh
    __shared__ __align__(16) ull   w1p[105 * 36];   // 30240B packed W1 col pairs
    __shared__ __align__(16) ull   w2p[70 * 18];    // 10080B packed W2 col pairs
    __shared__ __align__(16) ull   b1p[36];
    __shared__ __align__(16) ull   b2p[18];

    const int tid = threadIdx.x;
    for (int i = tid; i < 105 * 36; i += 256) {
        int k = i / 36, j = i % 36;
        int c = 2 * j;
        float v0 = (c < 70)     ? W1[k * 70 + c]     : 0.0f;
        float v1 = (c + 1 < 70) ? W1[k * 70 + c + 1] : 0.0f;
        w1p[i] = pack2(v0, v1);
    }
    for (int i = tid; i < 70 * 18; i += 256) {
        int k = i / 18, j = i % 18;
        int c = 2 * j;
        w2p[i] = pack2(W2[k * EMB + c], (c + 1 < EMB) ? W2[k * EMB + c + 1] : 0.0f);
    }
    if (tid < 36) {
        int c = 2 * tid;
        b1p[tid] = pack2((c < 70) ? b1[c] : 0.0f, (c + 1 < 70) ? b1[c + 1] : 0.0f);
    }
    if (tid < 18) {
        int c = 2 * tid;
        b2p[tid] = pack2(b2[c], (c + 1 < EMB) ? b2[c + 1] : 0.0f);
    }

    const int base = blockIdx.x * 128;

    // ---- stage X transposed as fp16: Xh[k*132 + node_l] ----
    for (int g = tid; g < 128 * 105; g += 256) {
        int nl = g / 105;
        int k  = g - nl * 105;
        int n  = base + nl;
        float v = 0.0f;
        if (n < 2 * NNODE) {
            if (n < NNODE) {
                if (k < EMB)          v = fa[n * EMB + k];
                else if (k < 2 * EMB) v = g_m[0][n * MSTR + (k - EMB)];
                else                  v = g_m[1][n * MSTR + (k - 2 * EMB)];
            } else {
                int nn = n - NNODE;
                if (k < EMB)          v = fb[nn * EMB + k];
                else if (k < 2 * EMB) v = g_m[2][nn * MSTR + (k - EMB)];
                else                  v = g_m[3][nn * MSTR + (k - 2 * EMB)];
            }
        }
        Xh[k * 132 + nl] = __float2half_rn(v);
    }
    __syncthreads();

    const int cg = tid >> 6;          // 0..3: column group (18 cols = 9 pairs)
    const int ng = tid & 63;          // 0..63: node pair
    const int n0 = base + 2 * ng;
    const float alpha = __ldg(alpha_p);

    // ---- GEMM1: 2 nodes x 9 pairs ----
    ull acc0[9], acc1[9];
#pragma unroll
    for (int i = 0; i < 9; i++) { acc0[i] = b1p[9 * cg + i]; acc1[i] = acc0[i]; }

    const ull* wbase = w1p + 9 * cg;
    for (int k = 0; k < 105; k++) {
        __half2 hv = *reinterpret_cast<const __half2*>(&Xh[k * 132 + 2 * ng]);
        float2 xv = __half22float2(hv);
        ull xx0 = pack2(xv.x, xv.x);
        ull xx1 = pack2(xv.y, xv.y);
        const ull* wr = wbase + k * 36;
#pragma unroll
        for (int i = 0; i < 9; i++) {
            ull w = wr[i];
            FMA2(acc0[i], w, xx0, acc0[i]);
            FMA2(acc1[i], w, xx1, acc1[i]);
        }
    }
    __syncthreads();   // all Xh reads complete; buffer becomes Hh

    // ---- PReLU, publish Hh[c][node_l] as fp16 ----
#pragma unroll
    for (int i = 0; i < 9; i++) {
        int c = 18 * cg + 2 * i;
        float h0, h1, g0, g1;
        unpack2(acc0[i], h0, h1);     // node n0
        unpack2(acc1[i], g0, g1);     // node n0+1
        h0 = (h0 > 0.0f) ? h0 : alpha * h0;
        h1 = (h1 > 0.0f) ? h1 : alpha * h1;
        g0 = (g0 > 0.0f) ? g0 : alpha * g0;
        g1 = (g1 > 0.0f) ? g1 : alpha * g1;
        __half2 p0 = __floats2half2_rn(h0, g0);   // row c, nodes (2ng, 2ng+1)
        __half2 p1 = __floats2half2_rn(h1, g1);   // row c+1
        *reinterpret_cast<__half2*>(&Xh[c * 132 + 2 * ng])       = p0;
        *reinterpret_cast<__half2*>(&Xh[(c + 1) * 132 + 2 * ng]) = p1;
    }
    __syncthreads();

    // ---- GEMM2: 2 nodes x np output pairs ----
    const int p0 = (cg < 2) ? cg * 5 : 10 + (cg - 2) * 4;
    const int np = (cg < 2) ? 5 : 4;

    ull a20[5], a21[5];
#pragma unroll
    for (int q = 0; q < 5; q++) {
        ull b = (q < np) ? b2p[p0 + q] : 0ull;
        a20[q] = b;
        a21[q] = b;
    }

    const ull* w2base = w2p + p0;
    for (int k = 0; k < 70; k++) {
        __half2 hv = *reinterpret_cast<const __half2*>(&Xh[k * 132 + 2 * ng]);
        float2 xv = __half22float2(hv);
        ull xx0 = pack2(xv.x, xv.x);
        ull xx1 = pack2(xv.y, xv.y);
        const ull* wr = w2base + k * 18;
#pragma unroll
        for (int q = 0; q < 5; q++) {
            if (q < np) {
                ull w = wr[q];
                FMA2(a20[q], w, xx0, a20[q]);
                FMA2(a21[q], w, xx1, a21[q]);
            }
        }
    }

    // ---- write both nodes' output slices ----
#pragma unroll
    for (int p = 0; p < 2; p++) {
        int n = n0 + p;
        if (n < 2 * NNODE) {
            float* orow = out + n * EMB;
#pragma unroll
            for (int q = 0; q < 5; q++) {
                if (q < np) {
                    float v0, v1;
                    unpack2(p ? a21[q] : a20[q], v0, v1);
                    int c = 2 * (p0 + q);
                    orow[c] = v0;
                    if (c + 1 < EMB) orow[c + 1] = v1;
                }
            }
        }
    }
}

// =====================================================================
// launch
// =====================================================================
extern "C" void kernel_launch(void* const* d_in, const int* in_sizes, int n_in,
                              void* d_out, int out_size) {
    const float* fa = (const float*)d_in[0];
    const float* fb = (const float*)d_in[1];

    TArgs t;
    const float* fsrc[4] = { fb, fb, fa, fa };
    const float* fdst[4] = { fa, fa, fb, fb };
    for (int j = 0; j < 4; j++) {
        t.fsrc[j] = fsrc[j];
        t.fdst[j] = fdst[j];
        t.W[j]   = (const float*)d_in[6 + 3 * j];
        t.b[j]   = (const float*)d_in[7 + 3 * j];
        t.att[j] = (const float*)d_in[8 + 3 * j];
    }
    AArgs a;
    a.dst[0] = (const int*)d_in[2];
    a.dst[1] = (const int*)d_in[3];
    a.dst[2] = (const int*)d_in[4];
    a.dst[3] = (const int*)d_in[5];

    const float* W1 = (const float*)d_in[18];
    const float* b1 = (const float*)d_in[19];
    const float* al = (const float*)d_in[20];
    const float* W2 = (const float*)d_in[21];
    const float* b2 = (const float*)d_in[22];
    float* out = (float*)d_out;

    dim3 tg((NNODE + 127) / 128, 4);
    transform_kernel<<<tg, 256>>>(t);

    dim3 ag((NNODE + 7) / 8, 4);
    agg_kernel<<<ag, 256>>>(a);

    dim3 ug((2 * NNODE + 127) / 128);
    update_kernel<<<ug, 256>>>(fa, fb, W1, b1, al, W2, b2, out);
}

// round 13
// speedup vs baseline: 1.1521x; 1.0164x over previous
#include <cuda_runtime.h>
#include <cuda_fp16.h>
#include <math.h>

#define NNODE 50000
#define EMB 35
#define DEG 32
#define NBH 36     // halves per nb row: 35 ch + s_b(fp16) at slot 35 = 72B = 9 ull
#define MSTR 36    // g_m row stride (floats)

typedef unsigned long long ull;

// ---------------- scratch (device globals; no runtime allocation) ----------------
__device__ __half g_nbh[4][NNODE * NBH];   // fp16 transformed rows; slot 35 carries s_b
__device__ float  g_sa[4][NNODE];          // src-side attention score
__device__ float  g_m [4][NNODE * MSTR];   // aggregation results (padded rows)

// ---------------- packed f32x2 helpers ----------------
static __device__ __forceinline__ ull pack2(float a, float b) {
    ull r;
    unsigned int lo = __float_as_uint(a), hi = __float_as_uint(b);
    asm("mov.b64 %0, {%1, %2};" : "=l"(r) : "r"(lo), "r"(hi));
    return r;
}
static __device__ __forceinline__ void unpack2(ull v, float &a, float &b) {
    unsigned int lo, hi;
    asm("mov.b64 {%0, %1}, %2;" : "=r"(lo), "=r"(hi) : "l"(v));
    a = __uint_as_float(lo);
    b = __uint_as_float(hi);
}
#define FMA2(d, a, b, c) \
    asm("fma.rn.f32x2 %0, %1, %2, %3;" : "=l"(d) : "l"(a), "l"(b), "l"(c))

// ---------------- kernel args ----------------
struct TArgs {
    const float* fsrc[4];
    const float* fdst[4];
    const float* W[4];
    const float* b[4];
    const float* att[4];
};
struct AArgs {
    const int* dst[4];
};

// =====================================================================
// Kernel 1: nb = fsrc @ W + b (fp16, s_b in slot 35); s_a = fdst.att_lo.
// Two-phase smem staging. W rows padded to 20 ull so each half's 9 pairs
// start 16B-aligned -> 4 LDS.128 + 1 LDS.64 per k (was 9 LDS.64).
// =====================================================================
__global__ __launch_bounds__(256) void transform_kernel(TArgs args) {
    const int jid = blockIdx.y;
    const float* __restrict__ bv  = args.b[jid];
    const float* __restrict__ att = args.att[jid];

    __shared__ __align__(16) float Xs[128 * 37];    // 18944B staged feature rows
    __shared__ __align__(16) ull wp[EMB * 20];      // 5600B padded packed W
    __shared__ __align__(16) ull bp[18];
    __shared__ __align__(16) ull ahp[18];
    __shared__ __align__(16) float alo[36];

    const int tid = threadIdx.x;
    {
        const float* __restrict__ W = args.W[jid];
        for (int r = tid; r < EMB * 18; r += 256) {
            int k = r / 18, i = r % 18, c = 2 * i;
            // half0 pairs -> slots 0..8, half1 pairs -> slots 10..18
            wp[k * 20 + i + (i >= 9 ? 1 : 0)] =
                pack2(W[k * EMB + c], (c + 1 < EMB) ? W[k * EMB + c + 1] : 0.0f);
        }
    }
    if (tid < 18) {
        int c = 2 * tid;
        bp[tid]  = pack2(bv[c],        (c + 1 < EMB) ? bv[c + 1]        : 0.0f);
        ahp[tid] = pack2(att[EMB + c], (c + 1 < EMB) ? att[EMB + c + 1] : 0.0f);
    }
    if (tid < 36) alo[tid] = (tid < EMB) ? att[tid] : 0.0f;

    const int base  = blockIdx.x * 128;
    const int nrows = min(128, NNODE - base);
    const int total = nrows * EMB;

    const int row_l = tid >> 1;
    const int half  = tid & 1;
    const bool valid = (row_l < nrows);
    const int rl = valid ? row_l : 0;
    const int row = base + rl;
    const float* xrs = Xs + rl * 37;

    // ---- phase A: stage fdst, compute s_a ----
    {
        const float* __restrict__ src = args.fdst[jid] + base * EMB;
        for (int g = tid; g < total; g += 256)
            Xs[(g / EMB) * 37 + (g % EMB)] = src[g];
    }
    __syncthreads();
    {
        float sa = 0.0f;
        const int k0 = half ? 18 : 0;
        const int k1 = half ? EMB : 18;
        for (int k = k0; k < k1; k++) sa = fmaf(xrs[k], alo[k], sa);
        sa += __shfl_xor_sync(0xffffffffu, sa, 1);
        if (valid && half == 0) g_sa[jid][row] = sa;
    }
    __syncthreads();

    // ---- phase B: stage fsrc, GEMM + s_b ----
    {
        const float* __restrict__ src = args.fsrc[jid] + base * EMB;
        for (int g = tid; g < total; g += 256)
            Xs[(g / EMB) * 37 + (g % EMB)] = src[g];
    }
    __syncthreads();

    ull acc[9];
#pragma unroll
    for (int i = 0; i < 9; i++) acc[i] = bp[9 * half + i];

    const int hoff = 10 * half;
#pragma unroll 5
    for (int k = 0; k < EMB; k++) {
        float xv = xrs[k];
        ull xx = pack2(xv, xv);
        const ull* wr = wp + k * 20 + hoff;
        const ulonglong2* w2v = reinterpret_cast<const ulonglong2*>(wr);
#pragma unroll
        for (int i = 0; i < 4; i++) {
            ulonglong2 wv = w2v[i];
            FMA2(acc[2 * i],     wv.x, xx, acc[2 * i]);
            FMA2(acc[2 * i + 1], wv.y, xx, acc[2 * i + 1]);
        }
        FMA2(acc[8], wr[8], xx, acc[8]);
    }

    float ps;
    {
        ull sp = 0ull;
#pragma unroll
        for (int i = 0; i < 9; i++) FMA2(sp, acc[i], ahp[9 * half + i], sp);
        float x0, y0;
        unpack2(sp, x0, y0);
        ps = x0 + y0;
        ps += __shfl_xor_sync(0xffffffffu, ps, 1);
    }

    if (valid) {
        unsigned int* r =
            reinterpret_cast<unsigned int*>(&g_nbh[jid][row * NBH]) + 9 * half;
#pragma unroll
        for (int i = 0; i < 9; i++) {
            float f0, f1;
            unpack2(acc[i], f0, f1);
            if (half == 1 && i == 8) f1 = ps;    // slot 35 := s_b
            __half2 h = __floats2half2_rn(f0, f1);
            r[i] = *reinterpret_cast<unsigned int*>(&h);
        }
    }
}

// =====================================================================
// Kernel 2 (unchanged): attention aggregation. One warp per node.
// =====================================================================
__global__ __launch_bounds__(256) void agg_kernel(AArgs args) {
    const int jid = blockIdx.y;
    const __half* __restrict__ nbh = g_nbh[jid];
    const ull* __restrict__ nb = reinterpret_cast<const ull*>(nbh);
    const float* __restrict__ sav = g_sa[jid];
    const int*   __restrict__ dst = args.dst[jid];
    float* __restrict__ m = g_m[jid];

    __shared__ float sw[8][36];
    __shared__ int   soff[8][36];

    const int wid  = threadIdx.x >> 5;
    const int lane = threadIdx.x & 31;
    const int node = blockIdx.x * 8 + wid;
    if (node >= NNODE) return;

    const int d = dst[node * DEG + lane];
    float sb = __half2float(nbh[d * NBH + 35]);
    float x = sav[node] + sb;
    float e = (x > 0.0f) ? x : 0.1f * expm1f(x);   // elu(alpha=0.1)
    float w = expf(e);

    float wsum = w;
#pragma unroll
    for (int o = 16; o; o >>= 1) wsum += __shfl_xor_sync(0xffffffffu, wsum, o);

    sw[wid][lane]   = w;
    soff[wid][lane] = d * 9;
    if (lane == 0) { sw[wid][32] = 0.0f; soff[wid][32] = 0; }
    __syncwarp();

    const int sub   = (lane < 27) ? (lane / 9) : 2;
    const int piece = (lane < 27) ? (lane % 9) : (lane - 27);

    float a0 = 0.0f, a1 = 0.0f, a2 = 0.0f, a3 = 0.0f;
#pragma unroll
    for (int it = 0; it < 11; it++) {
        int j = it * 3 + sub;
        float wj = sw[wid][j];
        ull v = nb[soff[wid][j] + piece];
        unsigned int lo, hi;
        asm("mov.b64 {%0, %1}, %2;" : "=r"(lo), "=r"(hi) : "l"(v));
        float2 f0 = __half22float2(*reinterpret_cast<__half2*>(&lo));
        float2 f1 = __half22float2(*reinterpret_cast<__half2*>(&hi));
        a0 = fmaf(wj, f0.x, a0);
        a1 = fmaf(wj, f0.y, a1);
        a2 = fmaf(wj, f1.x, a2);
        a3 = fmaf(wj, f1.y, a3);
    }

    {
        float t, u;
        t = __shfl_down_sync(0xffffffffu, a0, 9);
        u = __shfl_down_sync(0xffffffffu, a0, 18);
        a0 += t + u;
        t = __shfl_down_sync(0xffffffffu, a1, 9);
        u = __shfl_down_sync(0xffffffffu, a1, 18);
        a1 += t + u;
        t = __shfl_down_sync(0xffffffffu, a2, 9);
        u = __shfl_down_sync(0xffffffffu, a2, 18);
        a2 += t + u;
        t = __shfl_down_sync(0xffffffffu, a3, 9);
        u = __shfl_down_sync(0xffffffffu, a3, 18);
        a3 += t + u;
    }

    if (lane < 9) {
        float inv = 1.0f / wsum;
        float4 o = make_float4(a0 * inv, a1 * inv, a2 * inv, a3 * inv);
        *reinterpret_cast<float4*>(m + node * MSTR + 4 * lane) = o;
    }
}

// =====================================================================
// Kernel 3: register-tiled update, fp16 X/H staging, LDS.128 W reads.
// w1p rows padded to 40 ull (cg offset 10cg, 16B aligned);
// w2p rows padded to 20 ull (cg slots {0,6,12,16}).
// =====================================================================
__global__ __launch_bounds__(256, 3) void update_kernel(
    const float* __restrict__ fa, const float* __restrict__ fb,
    const float* __restrict__ W1, const float* __restrict__ b1,
    const float* __restrict__ alpha_p,
    const float* __restrict__ W2, const float* __restrict__ b2,
    float* __restrict__ out)
{
    __shared__ __align__(16) __half Xh[105 * 132];  // 27720B: Xh, then Hh
    __shared__ __align__(16) ull   w1p[105 * 40];   // 33600B padded packed W1
    __shared__ __align__(16) ull   w2p[70 * 20];    // 11200B padded packed W2
    __shared__ __align__(16) ull   b1p[36];
    __shared__ __align__(16) ull   b2p[18];

    const int tid = threadIdx.x;
    for (int i = tid; i < 105 * 36; i += 256) {
        int k = i / 36, j = i % 36;
        int c = 2 * j;
        float v0 = (c < 70)     ? W1[k * 70 + c]     : 0.0f;
        float v1 = (c + 1 < 70) ? W1[k * 70 + c + 1] : 0.0f;
        w1p[k * 40 + j + j / 9] = pack2(v0, v1);   // pad after every 9 pairs
    }
    for (int i = tid; i < 70 * 18; i += 256) {
        int k = i / 18, p = i % 18;
        int c = 2 * p;
        int slot = p + (p >= 5 ? 1 : 0) + (p >= 10 ? 1 : 0);  // {0-4,6-10,12-15,16-19}
        w2p[k * 20 + slot] =
            pack2(W2[k * EMB + c], (c + 1 < EMB) ? W2[k * EMB + c + 1] : 0.0f);
    }
    if (tid < 36) {
        int c = 2 * tid;
        b1p[tid] = pack2((c < 70) ? b1[c] : 0.0f, (c + 1 < 70) ? b1[c + 1] : 0.0f);
    }
    if (tid < 18) {
        int c = 2 * tid;
        b2p[tid] = pack2(b2[c], (c + 1 < EMB) ? b2[c + 1] : 0.0f);
    }

    const int base = blockIdx.x * 128;

    // ---- stage X transposed as fp16: Xh[k*132 + node_l] ----
    for (int g = tid; g < 128 * 105; g += 256) {
        int nl = g / 105;
        int k  = g - nl * 105;
        int n  = base + nl;
        float v = 0.0f;
        if (n < 2 * NNODE) {
            if (n < NNODE) {
                if (k < EMB)          v = fa[n * EMB + k];
                else if (k < 2 * EMB) v = g_m[0][n * MSTR + (k - EMB)];
                else                  v = g_m[1][n * MSTR + (k - 2 * EMB)];
            } else {
                int nn = n - NNODE;
                if (k < EMB)          v = fb[nn * EMB + k];
                else if (k < 2 * EMB) v = g_m[2][nn * MSTR + (k - EMB)];
                else                  v = g_m[3][nn * MSTR + (k - 2 * EMB)];
            }
        }
        Xh[k * 132 + nl] = __float2half_rn(v);
    }
    __syncthreads();

    const int cg = tid >> 6;          // 0..3: column group (9 pairs in GEMM1)
    const int ng = tid & 63;          // 0..63: node pair
    const int n0 = base + 2 * ng;
    const float alpha = __ldg(alpha_p);

    // ---- GEMM1: 2 nodes x 9 pairs ----
    ull acc0[9], acc1[9];
#pragma unroll
    for (int i = 0; i < 9; i++) { acc0[i] = b1p[9 * cg + i]; acc1[i] = acc0[i]; }

    const ull* wbase = w1p + 10 * cg;
    for (int k = 0; k < 105; k++) {
        __half2 hv = *reinterpret_cast<const __half2*>(&Xh[k * 132 + 2 * ng]);
        float2 xv = __half22float2(hv);
        ull xx0 = pack2(xv.x, xv.x);
        ull xx1 = pack2(xv.y, xv.y);
        const ull* wr = wbase + k * 40;
        const ulonglong2* wv2 = reinterpret_cast<const ulonglong2*>(wr);
#pragma unroll
        for (int i = 0; i < 4; i++) {
            ulonglong2 wv = wv2[i];
            FMA2(acc0[2 * i],     wv.x, xx0, acc0[2 * i]);
            FMA2(acc1[2 * i],     wv.x, xx1, acc1[2 * i]);
            FMA2(acc0[2 * i + 1], wv.y, xx0, acc0[2 * i + 1]);
            FMA2(acc1[2 * i + 1], wv.y, xx1, acc1[2 * i + 1]);
        }
        {
            ull w = wr[8];
            FMA2(acc0[8], w, xx0, acc0[8]);
            FMA2(acc1[8], w, xx1, acc1[8]);
        }
    }
    __syncthreads();   // all Xh reads complete; buffer becomes Hh

    // ---- PReLU, publish Hh[c][node_l] as fp16 ----
#pragma unroll
    for (int i = 0; i < 9; i++) {
        int c = 18 * cg + 2 * i;
        float h0, h1, g0, g1;
        unpack2(acc0[i], h0, h1);
        unpack2(acc1[i], g0, g1);
        h0 = (h0 > 0.0f) ? h0 : alpha * h0;
        h1 = (h1 > 0.0f) ? h1 : alpha * h1;
        g0 = (g0 > 0.0f) ? g0 : alpha * g0;
        g1 = (g1 > 0.0f) ? g1 : alpha * g1;
        __half2 p0 = __floats2half2_rn(h0, g0);
        __half2 p1 = __floats2half2_rn(h1, g1);
        *reinterpret_cast<__half2*>(&Xh[c * 132 + 2 * ng])       = p0;
        *reinterpret_cast<__half2*>(&Xh[(c + 1) * 132 + 2 * ng]) = p1;
    }
    __syncthreads();

    // ---- GEMM2: 2 nodes x np output pairs ----
    const int p0 = (cg < 2) ? cg * 5 : 10 + (cg - 2) * 4;
    const int np = (cg < 2) ? 5 : 4;
    const int soff = (cg < 2) ? cg * 6 : 12 + (cg - 2) * 4;  // {0,6,12,16}

    ull a20[5], a21[5];
#pragma unroll
    for (int q = 0; q < 5; q++) {
        ull b = (q < np) ? b2p[p0 + q] : 0ull;
        a20[q] = b;
        a21[q] = b;
    }

    const ull* w2base = w2p + soff;
    for (int k = 0; k < 70; k++) {
        __half2 hv = *reinterpret_cast<const __half2*>(&Xh[k * 132 + 2 * ng]);
        float2 xv = __half22float2(hv);
        ull xx0 = pack2(xv.x, xv.x);
        ull xx1 = pack2(xv.y, xv.y);
        const ull* wr = w2base + k * 20;
        const ulonglong2* wv2 = reinterpret_cast<const ulonglong2*>(wr);
#pragma unroll
        for (int i = 0; i < 2; i++) {
            ulonglong2 wv = wv2[i];
            FMA2(a20[2 * i],     wv.x, xx0, a20[2 * i]);
            FMA2(a21[2 * i],     wv.x, xx1, a21[2 * i]);
            FMA2(a20[2 * i + 1], wv.y, xx0, a20[2 * i + 1]);
            FMA2(a21[2 * i + 1], wv.y, xx1, a21[2 * i + 1]);
        }
        if (np == 5) {
            ull w = wr[4];
            FMA2(a20[4], w, xx0, a20[4]);
            FMA2(a21[4], w, xx1, a21[4]);
        }
    }

    // ---- write both nodes' output slices ----
#pragma unroll
    for (int p = 0; p < 2; p++) {
        int n = n0 + p;
        if (n < 2 * NNODE) {
            float* orow = out + n * EMB;
#pragma unroll
            for (int q = 0; q < 5; q++) {
                if (q < np) {
                    float v0, v1;
                    unpack2(p ? a21[q] : a20[q], v0, v1);
                    int c = 2 * (p0 + q);
                    orow[c] = v0;
                    if (c + 1 < EMB) orow[c + 1] = v1;
                }
            }
        }
    }
}

// =====================================================================
// launch
// =====================================================================
extern "C" void kernel_launch(void* const* d_in, const int* in_sizes, int n_in,
                              void* d_out, int out_size) {
    const float* fa = (const float*)d_in[0];
    const float* fb = (const float*)d_in[1];

    TArgs t;
    const float* fsrc[4] = { fb, fb, fa, fa };
    const float* fdst[4] = { fa, fa, fb, fb };
    for (int j = 0; j < 4; j++) {
        t.fsrc[j] = fsrc[j];
        t.fdst[j] = fdst[j];
        t.W[j]   = (const float*)d_in[6 + 3 * j];
        t.b[j]   = (const float*)d_in[7 + 3 * j];
        t.att[j] = (const float*)d_in[8 + 3 * j];
    }
    AArgs a;
    a.dst[0] = (const int*)d_in[2];
    a.dst[1] = (const int*)d_in[3];
    a.dst[2] = (const int*)d_in[4];
    a.dst[3] = (const int*)d_in[5];

    const float* W1 = (const float*)d_in[18];
    const float* b1 = (const float*)d_in[19];
    const float* al = (const float*)d_in[20];
    const float* W2 = (const float*)d_in[21];
    const float* b2 = (const float*)d_in[22];
    float* out = (float*)d_out;

    dim3 tg((NNODE + 127) / 128, 4);
    transform_kernel<<<tg, 256>>>(t);

    dim3 ag((NNODE + 7) / 8, 4);
    agg_kernel<<<ag, 256>>>(a);

    dim3 ug((2 * NNODE + 127) / 128);
    update_kernel<<<ug, 256>>>(fa, fb, W1, b1, al, W2, b2, out);
}